// round 9
// baseline (speedup 1.0000x reference)
#include <cuda_runtime.h>
#include <cstdint>

// knnLoss, single persistent kernel:
//   loss = sum_{b,t} min_s ||s-t||^2 / 120000
// Grid G^3 CSR binning, 3x3x3 exact box search (bound: source outside box is
// > h away, so best <= h^2*0.9995 proves exact min), inline warp-cooperative
// brute-force fallback for the ~0.3% tail targets. All phases fused via a
// software grid barrier (148 blocks == 1 per SM, guaranteed co-resident).

#define OUT_HW   100
#define STRIDE   4
#define NPTS     10000
#define NB       4
#define NBNPTS   (NB * NPTS)          // 40000
#define HW       400
#define PLANE    (HW * HW)
#define NALL     (2 * NBNPTS)         // 80000
#define G        16
#define G3       (G * G * G)          // 4096
#define NSEG     (8 * G3)             // 32768 (src segs 0..3, tgt segs 4..7)
#define RANGE    3.2f
#define HCELL    0.4f
#define INVH     2.5f
#define H2       (HCELL * HCELL)
#define FINF     3.4e38f

#define NBLK     148
#define NTHR     256
#define NTH      (NBLK * NTHR)        // 37888  (40000-37888 = 2112, 32-divisible)

__device__ float4 g_pt[NALL];
__device__ int    g_cid[NALL];
__device__ int    g_rank[NALL];
__device__ int    g_cnt[NSEG];
__device__ int    g_off[NSEG];
__device__ float4 g_sorted[NALL];
__device__ float  g_bpart[NBLK];

// Software grid barrier state. g_gen is monotonic across launches (never
// reset); g_arrive returns to 0 after every barrier.
__device__ unsigned g_arrive;
__device__ unsigned g_gen;

__device__ __forceinline__ void grid_barrier() {
    __syncthreads();
    if (threadIdx.x == 0) {
        unsigned gen = *(volatile unsigned*)&g_gen;   // snapshot BEFORE arrive
        __threadfence();                              // publish phase data + order snapshot
        if (atomicAdd(&g_arrive, 1u) == NBLK - 1) {
            g_arrive = 0;
            __threadfence();
            atomicAdd(&g_gen, 1u);                    // release
        } else {
            while (*(volatile unsigned*)&g_gen == gen) __nanosleep(64);
        }
        __threadfence();                              // acquire
    }
    __syncthreads();
}

__global__ void __launch_bounds__(NTHR)
knn_fused_kernel(const float* __restrict__ tgt,
                 const float* __restrict__ src,
                 float* __restrict__ out) {
    const int tid  = threadIdx.x;
    const int bid  = blockIdx.x;
    const int gtid = bid * NTHR + tid;
    const int lane = tid & 31;

    // ---- Phase 0: zero cell counts -------------------------------------
    for (int i = gtid; i < NSEG; i += NTH) g_cnt[i] = 0;
    grid_barrier();

    // ---- Phase 1: downsample + pack + bin-count ------------------------
    // which==0 -> sources (segs 0..3), which==1 -> targets (segs 4..7)
    for (int i = gtid; i < NALL; i += NTH) {
        int which = i / NBNPTS;
        int r = i - which * NBNPTS;
        int b = r / NPTS;
        int m = r - b * NPTS;
        int h = (m / OUT_HW) * STRIDE;
        int w = (m - (m / OUT_HW) * OUT_HW) * STRIDE;
        const float* p = (which == 0 ? src : tgt) + (size_t)b * 3 * PLANE + h * HW + w;
        float x = p[0];
        float y = p[PLANE];
        float z = p[2 * PLANE];
        float nrm = fmaf(x, x, fmaf(y, y, z * z));
        int cx = min(max((int)floorf((x + RANGE) * INVH), 0), G - 1);
        int cy = min(max((int)floorf((y + RANGE) * INVH), 0), G - 1);
        int cz = min(max((int)floorf((z + RANGE) * INVH), 0), G - 1);
        int cell = (which * NB + b) * G3 + (cz * G + cy) * G + cx;
        g_pt[i] = make_float4(x, y, z, nrm);
        g_cid[i] = cell;
        g_rank[i] = atomicAdd(&g_cnt[cell], 1);
    }
    grid_barrier();

    // ---- Phase 2: CSR exclusive scan over NSEG counts (block 0 only) ---
    if (bid == 0) {
        __shared__ int ts[NTHR];
        const int chunk = NSEG / NTHR;          // 128
        int base = tid * chunk;
        int s = 0;
        for (int k = 0; k < chunk; k++) s += g_cnt[base + k];
        ts[tid] = s;
        __syncthreads();
        #pragma unroll
        for (int st = 1; st < NTHR; st <<= 1) {
            int a = (tid >= st) ? ts[tid - st] : 0;
            __syncthreads();
            ts[tid] += a;
            __syncthreads();
        }
        int run = (tid == 0) ? 0 : ts[tid - 1];   // exclusive chunk base
        for (int k = 0; k < chunk; k++) {
            int c = g_cnt[base + k];
            g_off[base + k] = run;
            run += c;
        }
    }
    grid_barrier();

    // ---- Phase 3: scatter into CSR order -------------------------------
    for (int i = gtid; i < NALL; i += NTH)
        g_sorted[g_off[g_cid[i]] + g_rank[i]] = g_pt[i];
    grid_barrier();

    // ---- Phase 4: box search + inline warp fallback + local sum --------
    // Targets occupy g_sorted[NBNPTS..2*NBNPTS), cell-sorted (warp-coherent).
    // NBNPTS - NTH = 2112 is a multiple of 32 -> warp-uniform trip counts.
    float lsum = 0.0f;
    for (int j = gtid; j < NBNPTS; j += NTH) {
        float4 tv = g_sorted[NBNPTS + j];
        int b = j / NPTS;
        float ax = -2.0f * tv.x, ay = -2.0f * tv.y, az = -2.0f * tv.z;
        int cx = min(max((int)floorf((tv.x + RANGE) * INVH), 0), G - 1);
        int cy = min(max((int)floorf((tv.y + RANGE) * INVH), 0), G - 1);
        int cz = min(max((int)floorf((tv.z + RANGE) * INVH), 0), G - 1);
        int segbase = b * G3;
        int x0 = max(cx - 1, 0), x1 = min(cx + 1, G - 1);

        float best = FINF;
        #pragma unroll
        for (int dz = -1; dz <= 1; dz++) {
            int zz = min(max(cz + dz, 0), G - 1);   // clamp dup rows: harmless
            #pragma unroll
            for (int dy = -1; dy <= 1; dy++) {
                int yy = min(max(cy + dy, 0), G - 1);
                int row = segbase + (zz * G + yy) * G;
                int st = g_off[row + x0];
                int en = g_off[row + x1] + g_cnt[row + x1];
                for (int p = st; p < en; p++) {
                    float4 s = g_sorted[p];
                    float d = fmaf(s.x, ax, fmaf(s.y, ay, fmaf(s.z, az, s.w)));
                    best = fminf(best, d);
                }
            }
        }
        float full = best + tv.w;

        // Exactness bound not proven -> whole warp brute-scans that target.
        unsigned m = __ballot_sync(0xffffffffu, full > 0.9995f * H2);
        while (m) {
            int sl = __ffs(m) - 1;
            m &= m - 1;
            float bx = __shfl_sync(0xffffffffu, ax, sl);
            float by = __shfl_sync(0xffffffffu, ay, sl);
            float bz = __shfl_sync(0xffffffffu, az, sl);
            int   bb = __shfl_sync(0xffffffffu, b,  sl);
            const float4* sp = g_sorted + bb * NPTS;
            float mb = FINF;
            for (int p = lane; p < NPTS; p += 32) {
                float4 s = sp[p];
                mb = fminf(mb, fmaf(s.x, bx, fmaf(s.y, by, fmaf(s.z, bz, s.w))));
            }
            #pragma unroll
            for (int o = 16; o > 0; o >>= 1)
                mb = fminf(mb, __shfl_xor_sync(0xffffffffu, mb, o));
            if (lane == sl) full = mb + tv.w;
        }
        lsum += full;
    }

    // ---- Phase 5: block partial sums, then block-0 final reduce --------
    {
        __shared__ float red[NTHR];
        red[tid] = lsum;
        __syncthreads();
        #pragma unroll
        for (int s = NTHR / 2; s > 0; s >>= 1) {
            if (tid < s) red[tid] += red[tid + s];
            __syncthreads();
        }
        if (tid == 0) g_bpart[bid] = red[0];
    }
    grid_barrier();

    if (bid == 0 && tid == 0) {
        float tot = 0.0f;
        for (int i = 0; i < NBLK; i++) tot += g_bpart[i];   // fixed order
        out[0] = tot * (1.0f / (float)(NBNPTS * 3));
    }
}

// ---------------------------------------------------------------------------
extern "C" void kernel_launch(void* const* d_in, const int* in_sizes, int n_in,
                              void* d_out, int out_size) {
    const float* tgt = (const float*)d_in[0];   // target_pc (4,3,400,400)
    const float* src = (const float*)d_in[1];   // source_pc (4,3,400,400)
    float* out = (float*)d_out;
    knn_fused_kernel<<<NBLK, NTHR>>>(tgt, src, out);
}

// round 11
// speedup vs baseline: 5.2553x; 5.2553x over previous
#include <cuda_runtime.h>
#include <cstdint>

// knnLoss:  loss = sum_{b,t} min_s ||s-t||^2 / 120000  (exact).
// 3 graph nodes: memset(counts) -> pack(bin sources, copy targets)
//   -> search (3x3x3 box scan + warp-coop brute fallback + full reduce).
// Bins: fixed capacity per cell (no CSR scan/scatter). Exact stop bound:
// any source in an unscanned cell is >= h away (holds under clamping),
// so best <= 0.9995*h^2 proves the true min; else warp brute-scans.

#define OUT_HW   100
#define STRIDE   4
#define NPTS     10000
#define NB       4
#define NBNPTS   (NB * NPTS)          // 40000
#define HW       400
#define PLANE    (HW * HW)
#define NALL     (2 * NBNPTS)
#define G        16
#define G3       (G * G * G)          // 4096
#define NSEG     (NB * G3)            // 16384 source cells
#define CAP      96
#define RANGE    3.2f
#define HCELL    0.4f
#define INVH     2.5f
#define HBOUND   (0.9995f * HCELL * HCELL)
#define FINF     3.4e38f
#define NOVF_MAX 4096

#define SBLK     625                  // search blocks
#define STHR     128                  // 625*128 = 80000 = 2 threads/target

// Zeroed-per-call region: [0..NSEG) counts, [NSEG] overflow cnt, [NSEG+1] done.
__device__ int    g_zero[NSEG + 2];
__device__ float4 g_bins[NSEG * CAP];     // 25 MB, only cnt slots touched
__device__ float4 g_sflat[NBNPTS];        // sources, flat per batch
__device__ float4 g_t[NBNPTS];            // targets
__device__ float4 g_ovf[NOVF_MAX];
__device__ int    g_ovfb[NOVF_MAX];
__device__ float  g_bpart[SBLK];

// ---------------------------------------------------------------------------
// Pack: i < NBNPTS -> source (bin + flat copy); else target (copy only).
// ---------------------------------------------------------------------------
__global__ void __launch_bounds__(256)
pack_kernel(const float* __restrict__ tgt, const float* __restrict__ src) {
    int i = blockIdx.x * blockDim.x + threadIdx.x;
    if (i >= NALL) return;
    int which = i / NBNPTS;               // 0 = source, 1 = target
    int r = i - which * NBNPTS;
    int b = r / NPTS;
    int m = r - b * NPTS;
    int h = (m / OUT_HW) * STRIDE;
    int w = (m - (m / OUT_HW) * OUT_HW) * STRIDE;
    const float* p = (which == 0 ? src : tgt) + (size_t)b * 3 * PLANE + h * HW + w;
    float x = p[0];
    float y = p[PLANE];
    float z = p[2 * PLANE];
    float4 v = make_float4(x, y, z, fmaf(x, x, fmaf(y, y, z * z)));

    if (which == 1) { g_t[r] = v; return; }

    g_sflat[r] = v;
    int cx = min(max((int)floorf((x + RANGE) * INVH), 0), G - 1);
    int cy = min(max((int)floorf((y + RANGE) * INVH), 0), G - 1);
    int cz = min(max((int)floorf((z + RANGE) * INVH), 0), G - 1);
    int cell = b * G3 + (cz * G + cy) * G + cx;
    int rank = atomicAdd(&g_zero[cell], 1);
    if (rank < CAP) {
        g_bins[cell * CAP + rank] = v;
    } else {
        int o = atomicAdd(&g_zero[NSEG], 1);
        if (o < NOVF_MAX) { g_ovf[o] = v; g_ovfb[o] = b; }
    }
}

// ---------------------------------------------------------------------------
// Search: 2 threads per target. Pair splits the 27 box cells 14/14 (cell 13
// scanned by both halves; duplicates are harmless for min). Combine via
// shfl_xor(1). Fallback (bound unproven or clamped target): whole warp
// brute-scans that target's batch. Last block reduces everything.
// ---------------------------------------------------------------------------
__global__ void __launch_bounds__(STHR)
search_kernel(float* __restrict__ out) {
    __shared__ float red[STHR];
    __shared__ int slast;

    int gtid = blockIdx.x * STHR + threadIdx.x;
    int j    = gtid >> 1;                 // target id, < NBNPTS
    int half = gtid & 1;
    int lane = threadIdx.x & 31;

    float4 tv = g_t[j];
    int b = j / NPTS;
    float ax = -2.0f * tv.x, ay = -2.0f * tv.y, az = -2.0f * tv.z;

    int icx = (int)floorf((tv.x + RANGE) * INVH);
    int icy = (int)floorf((tv.y + RANGE) * INVH);
    int icz = (int)floorf((tv.z + RANGE) * INVH);
    int cx = min(max(icx, 0), G - 1);
    int cy = min(max(icy, 0), G - 1);
    int cz = min(max(icz, 0), G - 1);
    int tclamp = (icx != cx) | (icy != cy) | (icz != cz);
    int segbase = b * G3;

    float best = FINF;
    #pragma unroll
    for (int k = 0; k < 14; k++) {
        int c = half * 13 + k;            // 0..13 / 13..26
        int dz = c / 9, rem = c - dz * 9;
        int dy = rem / 3, dx = rem - dy * 3;
        int zz = min(max(cz + dz - 1, 0), G - 1);
        int yy = min(max(cy + dy - 1, 0), G - 1);
        int xx = min(max(cx + dx - 1, 0), G - 1);
        int cell = segbase + (zz * G + yy) * G + xx;
        int n = min(g_zero[cell], CAP);
        const float4* bp = g_bins + cell * CAP;
        for (int p = 0; p < n; p++) {
            float4 s = bp[p];
            best = fminf(best, fmaf(s.x, ax, fmaf(s.y, ay, fmaf(s.z, az, s.w))));
        }
    }
    // overflow points (normally none)
    int novf = min(g_zero[NSEG], NOVF_MAX);
    for (int o = 0; o < novf; o++) {
        if (g_ovfb[o] == b) {
            float4 s = g_ovf[o];
            best = fminf(best, fmaf(s.x, ax, fmaf(s.y, ay, fmaf(s.z, az, s.w))));
        }
    }
    best = fminf(best, __shfl_xor_sync(0xffffffffu, best, 1));
    float full = best + tv.w;

    // fallback: exactness bound not proven (or clamped target)
    unsigned need = __ballot_sync(0xffffffffu,
                                  ((full > HBOUND) | tclamp) && !(lane & 1));
    while (need) {
        int sl = __ffs(need) - 1;
        need &= need - 1;
        float bx = __shfl_sync(0xffffffffu, ax, sl);
        float by = __shfl_sync(0xffffffffu, ay, sl);
        float bz = __shfl_sync(0xffffffffu, az, sl);
        int   bb = __shfl_sync(0xffffffffu, b,  sl);
        const float4* sp = g_sflat + bb * NPTS;
        float mb = FINF;
        for (int p = lane; p < NPTS; p += 32) {
            float4 s = sp[p];
            mb = fminf(mb, fmaf(s.x, bx, fmaf(s.y, by, fmaf(s.z, bz, s.w))));
        }
        #pragma unroll
        for (int o = 16; o > 0; o >>= 1)
            mb = fminf(mb, __shfl_xor_sync(0xffffffffu, mb, o));
        float tw = __shfl_sync(0xffffffffu, tv.w, sl);
        if (lane == sl) full = mb + tw;
    }

    float lsum = (half == 0) ? full : 0.0f;

    // block reduction
    red[threadIdx.x] = lsum;
    __syncthreads();
    #pragma unroll
    for (int s = STHR / 2; s > 0; s >>= 1) {
        if (threadIdx.x < s) red[threadIdx.x] += red[threadIdx.x + s];
        __syncthreads();
    }
    if (threadIdx.x == 0) {
        g_bpart[blockIdx.x] = red[0];
        __threadfence();
        int o = atomicAdd(&g_zero[NSEG + 1], 1);
        slast = (o == SBLK - 1);
        __threadfence();
    }
    __syncthreads();

    if (slast) {                          // last block: fixed-order final sum
        float s = 0.0f;
        for (int i = threadIdx.x; i < SBLK; i += STHR) s += g_bpart[i];
        red[threadIdx.x] = s;
        __syncthreads();
        #pragma unroll
        for (int st = STHR / 2; st > 0; st >>= 1) {
            if (threadIdx.x < st) red[threadIdx.x] += red[threadIdx.x + st];
            __syncthreads();
        }
        if (threadIdx.x == 0)
            out[0] = red[0] * (1.0f / (float)(NBNPTS * 3));
    }
}

// ---------------------------------------------------------------------------
extern "C" void kernel_launch(void* const* d_in, const int* in_sizes, int n_in,
                              void* d_out, int out_size) {
    const float* tgt = (const float*)d_in[0];   // target_pc (4,3,400,400)
    const float* src = (const float*)d_in[1];   // source_pc (4,3,400,400)
    float* out = (float*)d_out;

    void* zaddr = nullptr;
    cudaGetSymbolAddress(&zaddr, g_zero);
    cudaMemsetAsync(zaddr, 0, (NSEG + 2) * sizeof(int));

    pack_kernel<<<(NALL + 255) / 256, 256>>>(tgt, src);
    search_kernel<<<SBLK, STHR>>>(out);
}